// round 16
// baseline (speedup 1.0000x reference)
#include <cuda_runtime.h>
#include <cuda_bf16.h>
#include <math.h>

#define L_SEQ 2049
#define BATCH 8
#define NH 16
#define HD 64
#define NS 128
#define DIN 1024
#define CONVD 1280
#define DPROJ 2320
#define NROWS 2056
#define GENEF 384
#define DMODEL 512
#define TCOR 2045   // corrected timesteps t=4..2048
#define TC 32       // scan chunk length
#define SST 24      // hgemm shared stride, bf16 elems (48B rows)

// ------------------------- scratch (static device globals) -------------------
__device__ float d_Z[2][NROWS * DPROJ];
__device__ float d_xBCs[2][(size_t)L_SEQ * CONVD];   // batch-shared conv out
__device__ float d_xBC0[BATCH * 4 * CONVD];          // fwd per-batch conv out, t=0..3
__device__ float d_dtr[2][NROWS * NH];
__device__ float d_dAr[2][NROWS * NH];
__device__ float d_ysum[2][(size_t)L_SEQ * NH * 64]; // scan y (each elem written once)
__device__ float d_ypre[BATCH * 3 * NH * 128];       // fwd per-batch y (t=1..3), halves
__device__ float d_decayf[NH * TCOR];                // cumprod dA fwd, t=4..2048
__device__ float d_dotCB[L_SEQ * 32];                // C_t . B_tau  [t][b][tau]
__device__ float d_W4[BATCH * NH * 4];               // dt_tau * prod dA  [b][h][tau]
__device__ float d_P[2][(size_t)2048 * DIN];         // silu(z) per gene row
__device__ float d_wcomb[2][DIN];
// split-bf16 operands for tensor-core GEMMs
__device__ __nv_bfloat16 d_Fhi[NROWS * GENEF];
__device__ __nv_bfloat16 d_Flo[NROWS * GENEF];
__device__ __nv_bfloat16 d_IWhi[DMODEL * GENEF];
__device__ __nv_bfloat16 d_IWlo[DMODEL * GENEF];
__device__ __nv_bfloat16 d_Xhi[NROWS * DMODEL];
__device__ __nv_bfloat16 d_Xlo[NROWS * DMODEL];
__device__ __nv_bfloat16 d_Whi[2][DPROJ * DMODEL];
__device__ __nv_bfloat16 d_Wlo[2][DPROJ * DMODEL];

__device__ __forceinline__ int seq_row(int b, int t) {
    return (t == 0) ? (2048 + b) : (t - 1);
}
__device__ __forceinline__ const float* xbc_fwd_ptr(int b, int t) {
    return (t >= 4) ? (d_xBCs[0] + (size_t)t * CONVD)
                    : (d_xBC0 + (size_t)(b * 4 + t) * CONVD);
}
// silu via hw tanh: silu(x) = 0.5x(1+tanh(x/2)) — 1 MUFU
__device__ __forceinline__ float fast_silu(float x) {
    float t;
    asm("tanh.approx.f32 %0, %1;" : "=f"(t) : "f"(x * 0.5f));
    return fmaf(0.5f * x, t, 0.5f * x);
}
__device__ __forceinline__ void store_split(__nv_bfloat16* hi, __nv_bfloat16* lo,
                                            size_t i, float v) {
    __nv_bfloat16 h = __float2bfloat16(v);
    hi[i] = h;
    lo[i] = __float2bfloat16(v - __bfloat162float(h));
}

// f32x2 packed math (sm_100+)
#define MUL2(d, a, b) asm("mul.rn.f32x2 %0,%1,%2;" : "=l"(d) : "l"(a), "l"(b))
#define FMA2(d, a, b, c) asm("fma.rn.f32x2 %0,%1,%2,%3;" : "=l"(d) : "l"(a), "l"(b), "l"(c))
#define ADD2(d, a, b) asm("add.rn.f32x2 %0,%1,%2;" : "=l"(d) : "l"(a), "l"(b))
__device__ __forceinline__ unsigned long long pack2(float x) {
    unsigned long long r;
    asm("mov.b64 %0,{%1,%1};" : "=l"(r) : "r"(__float_as_uint(x)));
    return r;
}
__device__ __forceinline__ float sum2(unsigned long long v) {
    unsigned int lo, hi;
    asm("mov.b64 {%0,%1},%2;" : "=r"(lo), "=r"(hi) : "l"(v));
    return __uint_as_float(lo) + __uint_as_float(hi);
}

// bf16 mma: D += A(m16k16) * B(n8k16)^T, f32 accum
#define MMA_BF16(cc, aa, bb) \
    asm volatile("mma.sync.aligned.m16n8k16.row.col.f32.bf16.bf16.f32 " \
        "{%0,%1,%2,%3}, {%4,%5,%6,%7}, {%8,%9}, {%0,%1,%2,%3};" \
        : "+f"((cc)[0]), "+f"((cc)[1]), "+f"((cc)[2]), "+f"((cc)[3]) \
        : "r"((aa)[0]), "r"((aa)[1]), "r"((aa)[2]), "r"((aa)[3]), \
          "r"((bb)[0]), "r"((bb)[1]))

#define LDSM_X4(r0, r1, r2, r3, addr) \
    asm volatile("ldmatrix.sync.aligned.m8n8.x4.shared.b16 {%0,%1,%2,%3}, [%4];" \
        : "=r"(r0), "=r"(r1), "=r"(r2), "=r"(r3) : "r"(addr))

__device__ __forceinline__ unsigned smem_u32(const void* p) {
    return (unsigned)__cvta_generic_to_shared(p);
}

#define CPA16(saddr, gptr) \
    asm volatile("cp.async.ca.shared.global [%0], [%1], 16;" :: "r"(saddr), "l"(gptr))
#define CPA4(saddr, gptr) \
    asm volatile("cp.async.ca.shared.global [%0], [%1], 4;" :: "r"(saddr), "l"(gptr))
#define CP_COMMIT() asm volatile("cp.async.commit_group;")
#define CP_WAIT0() asm volatile("cp.async.wait_group 0;")

// ------------------------- 1. feature rows (split-bf16 output) ---------------
__global__ void feat_kernel(const int* __restrict__ pidx,
                            const int* __restrict__ chridx,
                            const float* __restrict__ locus_fourier,
                            const float* __restrict__ pathway,
                            const float* __restrict__ pert_emb,
                            const float* __restrict__ gene_id,
                            const float* __restrict__ chr_emb,
                            const float* __restrict__ locus_w,
                            const float* __restrict__ locus_b,
                            const float* __restrict__ cond_w,
                            const float* __restrict__ cond_b) {
    int g = blockIdx.x;
    int tid = threadIdx.x;  // 128
    if (g < 2048) {
        store_split(d_Fhi, d_Flo, (size_t)g * GENEF + tid, gene_id[g * 128 + tid]);
        store_split(d_Fhi, d_Flo, (size_t)g * GENEF + 128 + tid, pathway[g * 128 + tid]);
        if (tid < 64) {
            int ci = chridx[g];
            store_split(d_Fhi, d_Flo, (size_t)g * GENEF + 256 + tid, chr_emb[ci * 64 + tid]);
        } else {
            int j = tid - 64;
            float acc = locus_b[j];
            const float* lf = locus_fourier + g * 64;
            const float* lw = locus_w + j * 64;
            for (int k = 0; k < 64; k++) acc = fmaf(lf[k], lw[k], acc);
            float ge = 0.5f * acc * (1.f + erff(acc * 0.70710678118654752f));
            store_split(d_Fhi, d_Flo, (size_t)g * GENEF + 320 + j, ge);
        }
    } else {
        int b = g - 2048;
        const float* pe = pert_emb + (size_t)pidx[b] * 128;
        for (int j = tid; j < GENEF; j += 128) {
            float acc = cond_b[j];
            const float* cw = cond_w + (size_t)j * 128;
            for (int k = 0; k < 128; k++) acc = fmaf(pe[k], cw[k], acc);
            store_split(d_Fhi, d_Flo, (size_t)g * GENEF + j, acc);
        }
    }
}

// ------------------------- 2a. weight conversions (merged) -------------------
__global__ void cvt_weights(const float* __restrict__ fw, const float* __restrict__ bw,
                            const float* __restrict__ iw) {
    int i = blockIdx.x * 256 + threadIdx.x;
    if (i < DPROJ * DMODEL) {
        store_split(d_Whi[0], d_Wlo[0], i, fw[i]);
        store_split(d_Whi[1], d_Wlo[1], i, bw[i]);
    }
    if (i < DMODEL * GENEF)
        store_split(d_IWhi, d_IWlo, i, iw[i]);
}

// ------------------------- 2b. tensor-core GEMM (cp.async, 1 barrier/chunk) --
template <int CFG>
__global__ __launch_bounds__(256) void hgemm(const float* __restrict__ bias) {
    constexpr int BM = (CFG == 0) ? 64 : 128;
    constexpr int MT = 2;
    constexpr int NT = (CFG == 0) ? 4 : 8;
    constexpr int NWC = (CFG == 0) ? 32 : 64;

    const __nv_bfloat16 *Ah, *Al, *Bh, *Bl;
    float* Cf = nullptr;
    float* Pf = nullptr;
    __nv_bfloat16 *Chi = nullptr, *Clo = nullptr;
    int M, N, K;
    if (CFG == 0) {
        Ah = d_Fhi; Al = d_Flo; Bh = d_IWhi; Bl = d_IWlo;
        Chi = d_Xhi; Clo = d_Xlo;
        M = NROWS; N = DMODEL; K = GENEF;
    } else {
        int dir = blockIdx.z;
        Ah = d_Xhi; Al = d_Xlo; Bh = d_Whi[dir]; Bl = d_Wlo[dir];
        Cf = d_Z[dir];
        Pf = d_P[dir];
        M = NROWS; N = DPROJ; K = DMODEL;
    }

    __shared__ __align__(16) __nv_bfloat16 sA[2][2][128 * SST];
    __shared__ __align__(16) __nv_bfloat16 sB[2][2][128 * SST];

    int tid = threadIdx.x;
    int row0 = blockIdx.y * BM;
    int col0 = blockIdx.x * 128;
    int lrow = tid >> 1;
    int seg = tid & 1;
    int lrowA = lrow & (BM - 1);

    int arow = row0 + lrowA;
    int brow = col0 + lrow;
    int arc = (arow < M) ? arow : (M - 1);
    int brc = (brow < N) ? brow : (N - 1);

    const __nv_bfloat16* pAh = Ah + (size_t)arc * K + seg * 8;
    const __nv_bfloat16* pAl = Al + (size_t)arc * K + seg * 8;
    const __nv_bfloat16* pBh = Bh + (size_t)brc * K + seg * 8;
    const __nv_bfloat16* pBl = Bl + (size_t)brc * K + seg * 8;

    unsigned dA0 = smem_u32(&sA[0][0][lrow * SST + seg * 8]);
    unsigned dA1 = smem_u32(&sA[0][1][lrow * SST + seg * 8]);
    unsigned dB0 = smem_u32(&sB[0][0][lrow * SST + seg * 8]);
    unsigned dB1 = smem_u32(&sB[0][1][lrow * SST + seg * 8]);
    const unsigned bufoff = (unsigned)(2 * 128 * SST * sizeof(__nv_bfloat16));

#define HG_STAGE(kc_, bb_)                                                     \
    {                                                                          \
        size_t o = (size_t)(kc_) * 16;                                         \
        unsigned bo = (bb_) ? bufoff : 0u;                                     \
        CPA16(dA0 + bo, pAh + o);                                              \
        CPA16(dA1 + bo, pAl + o);                                              \
        CPA16(dB0 + bo, pBh + o);                                              \
        CPA16(dB1 + bo, pBl + o);                                              \
    }

    HG_STAGE(0, 0);
    CP_COMMIT();

    int w = tid >> 5, l = tid & 31;
    int mw = (CFG == 0) ? (w >> 2) : (w >> 1);
    int nw = (CFG == 0) ? (w & 3) : (w & 1);
    int g = l >> 2, q = l & 3;

    int aoff = (mw * 32 + (l & 15)) * SST + (l >> 4) * 8;
    int boff = (nw * NWC + (l & 7) + (l >> 4) * 8) * SST + ((l >> 3) & 1) * 8;

    float c[MT][NT][4];
#pragma unroll
    for (int mt = 0; mt < MT; mt++)
#pragma unroll
        for (int nt = 0; nt < NT; nt++)
#pragma unroll
            for (int i = 0; i < 4; i++) c[mt][nt][i] = 0.f;

    const int NCH = K >> 4;
    for (int kc = 0; kc < NCH; kc++) {
        int buf = kc & 1;
        bool more = (kc + 1) < NCH;
        CP_WAIT0();
        __syncthreads();
        if (more) {
            HG_STAGE(kc + 1, buf ^ 1);
            CP_COMMIT();
        }

        unsigned a[MT][2][4], b[NT][2][2];
#pragma unroll
        for (int v = 0; v < 2; v++) {
#pragma unroll
            for (int mt = 0; mt < MT; mt++) {
                unsigned ad = smem_u32(&sA[buf][v][aoff + mt * 16 * SST]);
                LDSM_X4(a[mt][v][0], a[mt][v][1], a[mt][v][2], a[mt][v][3], ad);
            }
#pragma unroll
            for (int jp = 0; jp < NT / 2; jp++) {
                unsigned bd = smem_u32(&sB[buf][v][boff + jp * 16 * SST]);
                LDSM_X4(b[2 * jp][v][0], b[2 * jp][v][1],
                        b[2 * jp + 1][v][0], b[2 * jp + 1][v][1], bd);
            }
        }
#pragma unroll
        for (int mt = 0; mt < MT; mt++)
#pragma unroll
            for (int nt = 0; nt < NT; nt++) {
                MMA_BF16(c[mt][nt], a[mt][0], b[nt][0]);
                MMA_BF16(c[mt][nt], a[mt][0], b[nt][1]);
                MMA_BF16(c[mt][nt], a[mt][1], b[nt][0]);
            }
    }
#undef HG_STAGE

#pragma unroll
    for (int mt = 0; mt < MT; mt++) {
        int r0 = row0 + mw * 32 + mt * 16 + g;
#pragma unroll
        for (int nt = 0; nt < NT; nt++) {
            int cc = col0 + nw * NWC + nt * 8 + q * 2;
            if (cc >= N) continue;
            float b0 = bias ? bias[cc] : 0.f;
            float b1 = bias ? bias[cc + 1] : 0.f;
#pragma unroll
            for (int half = 0; half < 2; half++) {
                int r = r0 + half * 8;
                if (r >= M) continue;
                float v0 = c[mt][nt][half * 2 + 0] + b0;
                float v1 = c[mt][nt][half * 2 + 1] + b1;
                if (CFG != 0) {
                    if (cc < DIN) {
                        if (r < 2048) {
                            Pf[(size_t)r * DIN + cc] = fast_silu(v0);
                            Pf[(size_t)r * DIN + cc + 1] = fast_silu(v1);
                        }
                    } else {
                        *(float2*)&Cf[(size_t)r * N + cc] = make_float2(v0, v1);
                    }
                } else {
                    store_split(Chi, Clo, (size_t)r * N + cc, v0);
                    store_split(Chi, Clo, (size_t)r * N + cc + 1, v1);
                }
            }
        }
    }
}

// ------------------------- 3. causal depthwise conv + silu -------------------
__global__ void conv_kernel(const float* __restrict__ cw_f, const float* __restrict__ cb_f,
                            const float* __restrict__ cw_b, const float* __restrict__ cb_b) {
    int bx = blockIdx.x;
    int dir = blockIdx.y;
    const float* cw = dir ? cw_b : cw_f;
    const float* cb = dir ? cb_b : cb_f;
    const float* Z = d_Z[dir];

    const float* rows[4];
    float* dst;
    if (bx < L_SEQ) {
        int t = bx;
        if ((dir == 0 && t < 4) || (dir == 1 && t < 1)) return;
        dst = d_xBCs[dir] + (size_t)t * CONVD;
#pragma unroll
        for (int k = 0; k < 4; k++) {
            int tau = dir ? (t + 3 - k) : (t - 3 + k);
            rows[k] = (tau <= L_SEQ - 1) ? (Z + (size_t)(tau - 1) * DPROJ + DIN) : nullptr;
        }
    } else {
        if (dir == 1) return;
        int idx = bx - L_SEQ;
        int b = idx >> 2;
        int t = idx & 3;
        dst = d_xBC0 + (size_t)(b * 4 + t) * CONVD;
#pragma unroll
        for (int k = 0; k < 4; k++) {
            int tau = t - 3 + k;
            rows[k] = (tau >= 0) ? (Z + (size_t)seq_row(b, tau) * DPROJ + DIN) : nullptr;
        }
    }
    for (int c = threadIdx.x; c < CONVD; c += blockDim.x) {
        float acc = cb[c];
#pragma unroll
        for (int k = 0; k < 4; k++)
            if (rows[k]) acc = fmaf(rows[k][c], cw[c * 4 + k], acc);
        dst[c] = fast_silu(acc);
    }
}

// ------------------------- 4. dt / dA per row --------------------------------
__global__ void dtda_kernel(const float* __restrict__ fdtb, const float* __restrict__ fAl,
                            const float* __restrict__ bdtb, const float* __restrict__ bAl) {
    int idx = blockIdx.x * blockDim.x + threadIdx.x;
    const int per = NROWS * NH;
    if (idx >= 2 * per) return;
    int dir = idx / per;
    int r = idx % per;
    int row = r >> 4;
    int h = r & 15;
    float raw = d_Z[dir][(size_t)row * DPROJ + (DIN + CONVD) + h] + (dir ? bdtb : fdtb)[h];
    float dtv = (raw > 20.f) ? raw : log1pf(expf(raw));
    float Al = (dir ? bAl : fAl)[h];
    d_dtr[dir][row * NH + h] = dtv;
    d_dAr[dir][row * NH + h] = expf(-expf(Al) * dtv);
}

// ------------------------- 4b. fwd decay cumprod (parallel) ------------------
__global__ void decay_kernel() {
    int tid = threadIdx.x;    // 512
    int h = tid >> 5;
    int lane = tid & 31;
    int s0 = lane * 64;
    int len = (s0 < TCOR) ? ((TCOR - s0 < 64) ? (TCOR - s0) : 64) : 0;
    float prod = 1.f;
    for (int i = 0; i < len; i++) prod *= d_dAr[0][(size_t)(3 + s0 + i) * NH + h];
    float inc = prod;
#pragma unroll
    for (int off = 1; off < 32; off <<= 1) {
        float v = __shfl_up_sync(0xffffffffu, inc, off);
        if (lane >= off) inc *= v;
    }
    float excl = __shfl_up_sync(0xffffffffu, inc, 1);
    if (lane == 0) excl = 1.f;
    float run = excl;
    for (int i = 0; i < len; i++) {
        run *= d_dAr[0][(size_t)(3 + s0 + i) * NH + h];
        d_decayf[h * TCOR + s0 + i] = run;
    }
}

// ------------------------- 4c. W4 --------------------------------------------
__global__ void w4_kernel() {
    int idx = threadIdx.x;   // 512
    if (idx >= BATCH * NH * 4) return;
    int b = idx >> 6, h = (idx >> 2) & 15, tau = idx & 3;
    int row_tau = (tau == 0) ? (2048 + b) : (tau - 1);
    float w = d_dtr[0][row_tau * NH + h];
    for (int s = tau + 1; s < 4; s++)
        w *= d_dAr[0][(s - 1) * NH + h];
    d_W4[idx] = w;
}

// ------------------------- 4d. dotCB -----------------------------------------
__global__ void dotcb_kernel() {
    int t = blockIdx.x + 4;       // 4..2048
    __shared__ float sC[128];
    int tid = threadIdx.x;        // 256 = 8 warps
    if (tid < 128) sC[tid] = d_xBCs[0][(size_t)t * CONVD + DIN + NS + tid];
    __syncthreads();
    int w = tid >> 5, l = tid & 31;
    for (int c = w; c < 32; c += 8) {
        const float* B0 = d_xBC0 + (size_t)c * CONVD + DIN;
        float acc = 0.f;
#pragma unroll
        for (int i = 0; i < 4; i++) acc = fmaf(B0[i * 32 + l], sC[i * 32 + l], acc);
#pragma unroll
        for (int off = 16; off; off >>= 1)
            acc += __shfl_xor_sync(0xffffffffu, acc, off);
        if (l == 0) d_dotCB[t * 32 + c] = acc;
    }
}

// ------------------------- 5. combined output vector -------------------------
__global__ void wcomb_kernel(const float* __restrict__ head_w,
                             const float* __restrict__ fow, const float* __restrict__ bow,
                             const float* __restrict__ fnw, const float* __restrict__ bnw) {
    int idx = blockIdx.x * blockDim.x + threadIdx.x;
    if (idx >= 2 * DIN) return;
    int dir = idx >> 10;
    int j = idx & 1023;
    const float* ow = dir ? bow : fow;
    float acc = 0.f;
    for (int i = 0; i < DMODEL; i++) acc = fmaf(ow[(size_t)i * DIN + j], head_w[i], acc);
    d_wcomb[dir][j] = acc * (dir ? bnw : fnw)[j];
}

// ------------------------- 6a. fwd per-batch prefix scan (t=0..3) ------------
__global__ __launch_bounds__(128) void prefix_kernel(const float* __restrict__ fD) {
    int blk = blockIdx.x;
    int b = blk >> 4;
    int h = blk & 15;
    int tid = threadIdx.x;
    int p = tid & 63;
    int nh = tid >> 6;
    float Dh = fD[h];

    __shared__ __align__(16) float sB[128], sC[128], sx[64];

    unsigned long long hs2[32];
#pragma unroll
    for (int i = 0; i < 32; i++) hs2[i] = 0ull;

    for (int t = 0; t < 4; t++) {
        const float* pp = xbc_fwd_ptr(b, t);
        sB[tid] = pp[DIN + tid];
        sC[tid] = pp[DIN + NS + tid];
        if (tid < 64) sx[tid] = pp[h * HD + tid];
        __syncthreads();
        int row = (t == 0) ? (2048 + b) : (t - 1);
        float dtv = d_dtr[0][row * NH + h];
        float dAv = d_dAr[0][row * NH + h];
        float xv = sx[p];
        unsigned long long coef2 = pack2(dtv * xv);
        unsigned long long dA2 = pack2(dAv);
        const ulonglong2* B4 = (const ulonglong2*)(sB + nh * 64);
        const ulonglong2* C4 = (const ulonglong2*)(sC + nh * 64);
        unsigned long long a0 = 0ull, a1 = 0ull;
#pragma unroll
        for (int i = 0; i < 16; i++) {
            ulonglong2 bv = B4[i], cv = C4[i];
            unsigned long long tm;
            MUL2(tm, coef2, bv.x);
            FMA2(hs2[2 * i + 0], dA2, hs2[2 * i + 0], tm);
            FMA2(a0, hs2[2 * i + 0], cv.x, a0);
            MUL2(tm, coef2, bv.y);
            FMA2(hs2[2 * i + 1], dA2, hs2[2 * i + 1], tm);
            FMA2(a1, hs2[2 * i + 1], cv.y, a1);
        }
        ADD2(a0, a0, a1);
        float part = sum2(a0);
        if (nh == 0) part = fmaf(Dh, xv, part);
        if (t >= 1)
            d_ypre[((size_t)(b * 3 + (t - 1)) * 16 + h) * 128 + tid] = part;
        __syncthreads();
    }
}

// ------------------------- 6b. shared scans — cp.async + shfl reduce ---------
// 256 blocks = (dir, h, p-eighth pq). 128 threads: n16 = tid&15 (8 states each),
// p8g = tid>>4. Per chunk (TC=32): cp.async staging (double-buffered, 1
// barrier); per step: 12 f32x2 ops, butterfly-reduce over the 16-lane n-group,
// lane n16==0 stores the finished y directly (no shared partials).
__global__ __launch_bounds__(128) void scan_shared(const float* __restrict__ fD,
                                                   const float* __restrict__ bD) {
    int blk = blockIdx.x;          // 0..255
    int dir = blk >> 7;
    int rest = blk & 127;
    int h = rest >> 3;
    int pq = rest & 7;
    int tid = threadIdx.x;
    int n16 = tid & 15;
    int p8g = tid >> 4;            // 0..7
    float Dh = (dir ? bD : fD)[h];
    const float* xbc = d_xBCs[dir];
    const float* dtr = d_dtr[dir];
    const float* dAr = d_dAr[dir];
    float* ysum = d_ysum[dir];

    int S = dir ? 2048 : TCOR;
    int nch = (S + TC - 1) / TC;

    __shared__ __align__(16) float sB[2][TC][128];
    __shared__ __align__(16) float sC[2][TC][128];
    __shared__ __align__(16) float sx[2][TC][8];
    __shared__ float sdt[2][TC], sdA[2][TC];

    unsigned long long hs2[4] = {0ull, 0ull, 0ull, 0ull};

    // staging slots for this thread
    int bcj = tid >> 5;            // B/C base row per k-step (rows bcj + k*4)... see loop
    (void)bcj;

#define SCAN_STAGE(s0_, bb_)                                                    \
    {                                                                           \
        int lim = S - 1 - (s0_);                                                \
        _Pragma("unroll")                                                       \
        for (int k = 0; k < 8; k++) {                                           \
            int idx = tid + k * 128;                                            \
            int jr = idx >> 5;                                                  \
            int j = (jr > lim) ? lim : jr;                                      \
            int tt = dir ? (2048 - ((s0_) + j)) : (4 + (s0_) + j);              \
            const float* gB = xbc + (size_t)tt * CONVD + DIN + (idx & 31) * 4;  \
            CPA16(smem_u32(&sB[bb_][jr][(idx & 31) * 4]), gB);                  \
            CPA16(smem_u32(&sC[bb_][jr][(idx & 31) * 4]), gB + NS);             \
        }                                                                       \
        if (tid < 2 * TC) {                                                     \
            int jr = tid >> 1;                                                  \
            int j = (jr > lim) ? lim : jr;                                      \
            int tt = dir ? (2048 - ((s0_) + j)) : (4 + (s0_) + j);              \
            const float* gx = xbc + (size_t)tt * CONVD + h * HD + pq * 8 +      \
                              (tid & 1) * 4;                                    \
            CPA16(smem_u32(&sx[bb_][jr][(tid & 1) * 4]), gx);                   \
        }                                                                       \
        if (tid < TC) {                                                         \
            int j = (tid > lim) ? lim : tid;                                    \
            int tt = dir ? (2048 - ((s0_) + j)) : (4 + (s0_) + j);              \
            CPA4(smem_u32(&sdt[bb_][tid]), dtr + (tt - 1) * NH + h);            \
            CPA4(smem_u32(&sdA[bb_][tid]), dAr + (tt - 1) * NH + h);            \
        }                                                                       \
    }

    SCAN_STAGE(0, 0);
    CP_COMMIT();

    for (int c = 0; c < nch; c++) {
        int s0 = c * TC;
        int cnt = (S - s0 < TC) ? (S - s0) : TC;
        bool more = (c + 1) < nch;
        int bb = c & 1;
        CP_WAIT0();
        __syncthreads();
        if (more) {
            SCAN_STAGE(s0 + TC, bb ^ 1);
            CP_COMMIT();
        }
        for (int j = 0; j < cnt; j++) {
            float xv = sx[bb][j][p8g];
            unsigned long long coef2 = pack2(sdt[bb][j] * xv);
            unsigned long long dA2 = pack2(sdA[bb][j]);
            const ulonglong2* B4 = (const ulonglong2*)&sB[bb][j][n16 * 8];
            const ulonglong2* C4 = (const ulonglong2*)&sC[bb][j][n16 * 8];
            ulonglong2 bv0 = B4[0], cv0 = C4[0];
            ulonglong2 bv1 = B4[1], cv1 = C4[1];
            unsigned long long a0 = 0ull, a1 = 0ull, tm;
            MUL2(tm, coef2, bv0.x);
            FMA2(hs2[0], dA2, hs2[0], tm);
            FMA2(a0, hs2[0], cv0.x, a0);
            MUL2(tm, coef2, bv0.y);
            FMA2(hs2[1], dA2, hs2[1], tm);
            FMA2(a1, hs2[1], cv0.y, a1);
            MUL2(tm, coef2, bv1.x);
            FMA2(hs2[2], dA2, hs2[2], tm);
            FMA2(a0, hs2[2], cv1.x, a0);
            MUL2(tm, coef2, bv1.y);
            FMA2(hs2[3], dA2, hs2[3], tm);
            FMA2(a1, hs2[3], cv1.y, a1);
            ADD2(a0, a0, a1);
            float part = sum2(a0);
            // butterfly reduce over the 16-lane n-group
            part += __shfl_xor_sync(0xffffffffu, part, 8);
            part += __shfl_xor_sync(0xffffffffu, part, 4);
            part += __shfl_xor_sync(0xffffffffu, part, 2);
            part += __shfl_xor_sync(0xffffffffu, part, 1);
            if (n16 == 0) {
                float s = fmaf(Dh, xv, part);
                int tt = dir ? (2048 - (s0 + j)) : (4 + s0 + j);
                ysum[(size_t)tt * 1024 + h * 64 + pq * 8 + p8g] = s;
            }
        }
    }
#undef SCAN_STAGE
}

// ------------------------- 7. gate + RMSnorm + fused head (per-t, all b) -----
__global__ __launch_bounds__(256) void final_kernel(const float* __restrict__ head_b,
                                                    float* __restrict__ out) {
    int t = blockIdx.x + 1;     // 1..2048
    int tid = threadIdx.x;      // 256
    __shared__ float cco[8][64];
    __shared__ float sh[8][18];

    if (t >= 4) {
        for (int i = tid; i < 512; i += 256) {
            int b = i >> 6;
            int r = i & 63;             // h*4+tau
            int hh = r >> 2, tau = r & 3;
            cco[b][r] = d_decayf[hh * TCOR + (t - 4)] *
                        d_W4[(b * 16 + hh) * 4 + tau] *
                        d_dotCB[t * 32 + b * 4 + tau];
        }
    }
    __syncthreads();

    int j0 = tid * 4;
    int h = tid >> 4;
    float4 ysf4 = *(const float4*)&d_ysum[0][(size_t)t * DIN + j0];
    float4 ysb4 = *(const float4*)&d_ysum[1][(size_t)t * DIN + j0];
    float4 pf4 = *(const float4*)&d_P[0][(size_t)(t - 1) * DIN + j0];
    float4 pb4 = *(const float4*)&d_P[1][(size_t)(t - 1) * DIN + j0];
    float4 w04 = *(const float4*)&d_wcomb[0][j0];
    float4 w14 = *(const float4*)&d_wcomb[1][j0];

    float ssqb = 0.f, sdotb = 0.f;
    {
        float g;
        g = ysb4.x * pb4.x; ssqb = fmaf(g, g, ssqb); sdotb = fmaf(g, w14.x, sdotb);
        g = ysb4.y * pb4.y; ssqb = fmaf(g, g, ssqb); sdotb = fmaf(g, w14.y, sdotb);
        g = ysb4.z * pb4.z; ssqb = fmaf(g, g, ssqb); sdotb = fmaf(g, w14.z, sdotb);
        g = ysb4.w * pb4.w; ssqb = fmaf(g, g, ssqb); sdotb = fmaf(g, w14.w, sdotb);
    }

    float ssqf[8], sdotf[8];
    if (t >= 4) {
#pragma unroll
        for (int b = 0; b < 8; b++) {
            const float* xbb = d_xBC0 + (size_t)b * 4 * CONVD + j0;
            float4 x0 = *(const float4*)&xbb[0];
            float4 x1 = *(const float4*)&xbb[CONVD];
            float4 x2 = *(const float4*)&xbb[2 * CONVD];
            float4 x3 = *(const float4*)&xbb[3 * CONVD];
            float cc0 = cco[b][h * 4 + 0], cc1 = cco[b][h * 4 + 1];
            float cc2 = cco[b][h * 4 + 2], cc3 = cco[b][h * 4 + 3];
            float sq = 0.f, sd = 0.f, yf, g;
            yf = ysf4.x + cc0 * x0.x + cc1 * x1.x + cc2 * x2.x + cc3 * x3.x;
            g = yf * pf4.x; sq = fmaf(g, g, sq); sd = fmaf(g, w04.x, sd);
            yf = ysf4.y + cc0 * x0.y + cc1 * x1.y + cc2 * x2.y + cc3 * x3.y;
            g = yf * pf4.y; sq = fmaf(g, g, sq); sd = fmaf(g, w04.y, sd);
            yf = ysf4.z + cc0 * x0.z + cc1 * x1.z + cc2 * x2.z + cc3 * x3.z;
            g = yf * pf4.z; sq = fmaf(g, g, sq); sd = fmaf(g, w04.z, sd);
            yf = ysf4.w + cc0 * x0.w + cc1 * x1.w + cc2 * x2.w + cc3 * x3.w;
            g = yf * pf4.w; sq = fmaf(g, g, sq); sd = fmaf(g, w04.w, sd);
            ssqf[b] = sq; sdotf[b] = sd;
        }
    } else {
        int p0 = j0 & 63;
#pragma unroll
        for (int b = 0; b < 8; b++) {
            const float* yp = d_ypre + ((size_t)(b * 3 + (t - 1)) * 16 + h) * 128;
            float sq = 0.f, sd = 0.f;
            float pf[4] = {pf4.x, pf4.y, pf4.z, pf4.w};
            float w0[4] = {w04.x, w04.y, w04.z, w04.w};
#pragma unroll
            for (int k = 0; k < 4; k++) {
                float yf = yp[p0 + k] + yp[64 + p0 + k];
                float g = yf * pf[k];
                sq = fmaf(g, g, sq); sd = fmaf(g, w0[k], sd);
            }
            ssqf[b] = sq; sdotf[b] = sd;
        }
    }

#pragma unroll
    for (int off = 16; off; off >>= 1) {
        ssqb += __shfl_xor_sync(0xffffffffu, ssqb, off);
        sdotb += __shfl_xor_sync(0xffffffffu, sdotb, off);
#pragma unroll
        for (int b = 0; b < 8; b++) {
            ssqf[b] += __shfl_xor_sync(0xffffffffu, ssqf[b], off);
            sdotf[b] += __shfl_xor_sync(0xffffffffu, sdotf[b], off);
        }
    }
    int w = tid >> 5, l = tid & 31;
    if (l == 0) {
        sh[w][0] = ssqb; sh[w][1] = sdotb;
#pragma unroll
        for (int b = 0; b < 8; b++) { sh[w][2 + b] = ssqf[b]; sh[w][10 + b] = sdotf[b]; }
    }
    __syncthreads();
    if (tid < 8) {
        float qb = 0.f, db = 0.f, a = 0.f, d = 0.f;
        for (int i = 0; i < 8; i++) {
            qb += sh[i][0]; db += sh[i][1];
            a += sh[i][2 + tid]; d += sh[i][10 + tid];
        }
        float resb = rsqrtf(qb * (1.f / 1024.f) + 1e-5f) * db;
        float resf = rsqrtf(a * (1.f / 1024.f) + 1e-5f) * d;
        out[tid * 2048 + (t - 1)] = resf + resb + head_b[0];
    }
}

// ------------------------- launch --------------------------------------------
extern "C" void kernel_launch(void* const* d_in, const int* in_sizes, int n_in,
                              void* d_out, int out_size) {
    const int* pidx            = (const int*)d_in[0];
    const int* chridx          = (const int*)d_in[1];
    const float* locus_fourier = (const float*)d_in[2];
    const float* pathway       = (const float*)d_in[3];
    const float* pert_emb      = (const float*)d_in[4];
    const float* gene_id       = (const float*)d_in[5];
    const float* chr_emb       = (const float*)d_in[6];
    const float* locus_w       = (const float*)d_in[7];
    const float* locus_b       = (const float*)d_in[8];
    const float* cond_w        = (const float*)d_in[9];
    const float* cond_b        = (const float*)d_in[10];
    const float* in_w          = (const float*)d_in[11];
    const float* in_b          = (const float*)d_in[12];
    const float* head_w        = (const float*)d_in[13];
    const float* head_b        = (const float*)d_in[14];
    const float* f_in_w        = (const float*)d_in[15];
    const float* f_conv_w      = (const float*)d_in[16];
    const float* f_conv_b      = (const float*)d_in[17];
    const float* f_dt_bias     = (const float*)d_in[18];
    const float* f_A_log       = (const float*)d_in[19];
    const float* f_D           = (const float*)d_in[20];
    const float* f_norm_w      = (const float*)d_in[21];
    const float* f_out_w       = (const float*)d_in[22];
    const float* b_in_w        = (const float*)d_in[23];
    const float* b_conv_w      = (const float*)d_in[24];
    const float* b_conv_b      = (const float*)d_in[25];
    const float* b_dt_bias     = (const float*)d_in[26];
    const float* b_A_log       = (const float*)d_in[27];
    const float* b_D           = (const float*)d_in[28];
    const float* b_norm_w      = (const float*)d_in[29];
    const float* b_out_w       = (const float*)d_in[30];
    float* out = (float*)d_out;

    feat_kernel<<<NROWS, 128>>>(pidx, chridx, locus_fourier, pathway, pert_emb,
                                gene_id, chr_emb, locus_w, locus_b, cond_w, cond_b);
    cvt_weights<<<(DPROJ * DMODEL + 255) / 256, 256>>>(f_in_w, b_in_w, in_w);

    // X = feat @ in_w^T + in_b (64x128 tiles, cp.async staging)
    hgemm<0><<<dim3(4, 33), 256>>>(in_b);
    // Z_dir = X @ W^T (128x128 tiles, both dirs; z-cols -> silu -> d_P fused)
    hgemm<1><<<dim3(19, 17, 2), 256>>>(nullptr);

    conv_kernel<<<dim3(L_SEQ + 32, 2), 256>>>(f_conv_w, f_conv_b, b_conv_w, b_conv_b);

    dtda_kernel<<<(2 * NROWS * NH + 255) / 256, 256>>>(f_dt_bias, f_A_log, b_dt_bias, b_A_log);
    decay_kernel<<<1, 512>>>();
    w4_kernel<<<1, 512>>>();
    dotcb_kernel<<<TCOR, 256>>>();

    wcomb_kernel<<<(2 * DIN + 255) / 256, 256>>>(head_w, f_out_w, b_out_w, f_norm_w, b_norm_w);

    prefix_kernel<<<128, 128>>>(f_D);

    // cp.async-staged scans with in-warp n-reduction (one barrier per 32 steps)
    scan_shared<<<256, 128>>>(f_D, b_D);

    final_kernel<<<2048, 256>>>(head_b, out);
}

// round 17
// speedup vs baseline: 1.4585x; 1.4585x over previous
#include <cuda_runtime.h>
#include <cuda_bf16.h>
#include <math.h>

#define L_SEQ 2049
#define BATCH 8
#define NH 16
#define HD 64
#define NS 128
#define DIN 1024
#define CONVD 1280
#define DPROJ 2320
#define NROWS 2056
#define GENEF 384
#define DMODEL 512
#define TCOR 2045   // corrected timesteps t=4..2048
#define TC 16       // scan chunk length
#define SST 24      // hgemm shared stride, bf16 elems (48B rows)

// ------------------------- scratch (static device globals) -------------------
__device__ float d_Z[2][NROWS * DPROJ];
__device__ float d_xBCs[2][(size_t)L_SEQ * CONVD];   // batch-shared conv out
__device__ float d_xBC0[BATCH * 4 * CONVD];          // fwd per-batch conv out, t=0..3
__device__ float d_dtr[2][NROWS * NH];
__device__ float d_dAr[2][NROWS * NH];
__device__ float d_ysum[2][(size_t)L_SEQ * NH * 64]; // scan y (each elem written once)
__device__ float d_ypre[BATCH * 3 * NH * 128];       // fwd per-batch y (t=1..3), halves
__device__ float d_decayf[NH * TCOR];                // cumprod dA fwd, t=4..2048
__device__ float d_dotCB[L_SEQ * 32];                // C_t . B_tau  [t][b][tau]
__device__ float d_W4[BATCH * NH * 4];               // dt_tau * prod dA  [b][h][tau]
__device__ float d_P[2][(size_t)2048 * DIN];         // silu(z) per gene row
__device__ float d_wcomb[2][DIN];
// split-bf16 operands for tensor-core GEMMs
__device__ __nv_bfloat16 d_Fhi[NROWS * GENEF];
__device__ __nv_bfloat16 d_Flo[NROWS * GENEF];
__device__ __nv_bfloat16 d_IWhi[DMODEL * GENEF];
__device__ __nv_bfloat16 d_IWlo[DMODEL * GENEF];
__device__ __nv_bfloat16 d_Xhi[NROWS * DMODEL];
__device__ __nv_bfloat16 d_Xlo[NROWS * DMODEL];
__device__ __nv_bfloat16 d_Whi[2][DPROJ * DMODEL];
__device__ __nv_bfloat16 d_Wlo[2][DPROJ * DMODEL];

__device__ __forceinline__ int seq_row(int b, int t) {
    return (t == 0) ? (2048 + b) : (t - 1);
}
__device__ __forceinline__ const float* xbc_fwd_ptr(int b, int t) {
    return (t >= 4) ? (d_xBCs[0] + (size_t)t * CONVD)
                    : (d_xBC0 + (size_t)(b * 4 + t) * CONVD);
}
// silu via hw tanh: silu(x) = 0.5x(1+tanh(x/2)) — 1 MUFU
__device__ __forceinline__ float fast_silu(float x) {
    float t;
    asm("tanh.approx.f32 %0, %1;" : "=f"(t) : "f"(x * 0.5f));
    return fmaf(0.5f * x, t, 0.5f * x);
}
__device__ __forceinline__ void store_split(__nv_bfloat16* hi, __nv_bfloat16* lo,
                                            size_t i, float v) {
    __nv_bfloat16 h = __float2bfloat16(v);
    hi[i] = h;
    lo[i] = __float2bfloat16(v - __bfloat162float(h));
}

// f32x2 packed math (sm_100+)
#define MUL2(d, a, b) asm("mul.rn.f32x2 %0,%1,%2;" : "=l"(d) : "l"(a), "l"(b))
#define FMA2(d, a, b, c) asm("fma.rn.f32x2 %0,%1,%2,%3;" : "=l"(d) : "l"(a), "l"(b), "l"(c))
#define ADD2(d, a, b) asm("add.rn.f32x2 %0,%1,%2;" : "=l"(d) : "l"(a), "l"(b))
__device__ __forceinline__ unsigned long long pack2(float x) {
    unsigned long long r;
    asm("mov.b64 %0,{%1,%1};" : "=l"(r) : "r"(__float_as_uint(x)));
    return r;
}
__device__ __forceinline__ float sum2(unsigned long long v) {
    unsigned int lo, hi;
    asm("mov.b64 {%0,%1},%2;" : "=r"(lo), "=r"(hi) : "l"(v));
    return __uint_as_float(lo) + __uint_as_float(hi);
}

// bf16 mma: D += A(m16k16) * B(n8k16)^T, f32 accum
#define MMA_BF16(cc, aa, bb) \
    asm volatile("mma.sync.aligned.m16n8k16.row.col.f32.bf16.bf16.f32 " \
        "{%0,%1,%2,%3}, {%4,%5,%6,%7}, {%8,%9}, {%0,%1,%2,%3};" \
        : "+f"((cc)[0]), "+f"((cc)[1]), "+f"((cc)[2]), "+f"((cc)[3]) \
        : "r"((aa)[0]), "r"((aa)[1]), "r"((aa)[2]), "r"((aa)[3]), \
          "r"((bb)[0]), "r"((bb)[1]))

#define LDSM_X4(r0, r1, r2, r3, addr) \
    asm volatile("ldmatrix.sync.aligned.m8n8.x4.shared.b16 {%0,%1,%2,%3}, [%4];" \
        : "=r"(r0), "=r"(r1), "=r"(r2), "=r"(r3) : "r"(addr))

__device__ __forceinline__ unsigned smem_u32(const void* p) {
    return (unsigned)__cvta_generic_to_shared(p);
}

#define CPA16(saddr, gptr) \
    asm volatile("cp.async.ca.shared.global [%0], [%1], 16;" :: "r"(saddr), "l"(gptr))
#define CP_COMMIT() asm volatile("cp.async.commit_group;")
#define CP_WAIT0() asm volatile("cp.async.wait_group 0;")

// ------------------------- 1. feature rows (split-bf16 output) ---------------
__global__ void feat_kernel(const int* __restrict__ pidx,
                            const int* __restrict__ chridx,
                            const float* __restrict__ locus_fourier,
                            const float* __restrict__ pathway,
                            const float* __restrict__ pert_emb,
                            const float* __restrict__ gene_id,
                            const float* __restrict__ chr_emb,
                            const float* __restrict__ locus_w,
                            const float* __restrict__ locus_b,
                            const float* __restrict__ cond_w,
                            const float* __restrict__ cond_b) {
    int g = blockIdx.x;
    int tid = threadIdx.x;  // 128
    if (g < 2048) {
        store_split(d_Fhi, d_Flo, (size_t)g * GENEF + tid, gene_id[g * 128 + tid]);
        store_split(d_Fhi, d_Flo, (size_t)g * GENEF + 128 + tid, pathway[g * 128 + tid]);
        if (tid < 64) {
            int ci = chridx[g];
            store_split(d_Fhi, d_Flo, (size_t)g * GENEF + 256 + tid, chr_emb[ci * 64 + tid]);
        } else {
            int j = tid - 64;
            float acc = locus_b[j];
            const float* lf = locus_fourier + g * 64;
            const float* lw = locus_w + j * 64;
            for (int k = 0; k < 64; k++) acc = fmaf(lf[k], lw[k], acc);
            float ge = 0.5f * acc * (1.f + erff(acc * 0.70710678118654752f));
            store_split(d_Fhi, d_Flo, (size_t)g * GENEF + 320 + j, ge);
        }
    } else {
        int b = g - 2048;
        const float* pe = pert_emb + (size_t)pidx[b] * 128;
        for (int j = tid; j < GENEF; j += 128) {
            float acc = cond_b[j];
            const float* cw = cond_w + (size_t)j * 128;
            for (int k = 0; k < 128; k++) acc = fmaf(pe[k], cw[k], acc);
            store_split(d_Fhi, d_Flo, (size_t)g * GENEF + j, acc);
        }
    }
}

// ------------------------- 2a. weight conversions (merged) -------------------
__global__ void cvt_weights(const float* __restrict__ fw, const float* __restrict__ bw,
                            const float* __restrict__ iw) {
    int i = blockIdx.x * 256 + threadIdx.x;
    if (i < DPROJ * DMODEL) {
        store_split(d_Whi[0], d_Wlo[0], i, fw[i]);
        store_split(d_Whi[1], d_Wlo[1], i, bw[i]);
    }
    if (i < DMODEL * GENEF)
        store_split(d_IWhi, d_IWlo, i, iw[i]);
}

// ------------------------- 2b. tensor-core GEMM (cp.async, 1 barrier/chunk) --
template <int CFG>
__global__ __launch_bounds__(256) void hgemm(const float* __restrict__ bias) {
    constexpr int BM = (CFG == 0) ? 64 : 128;
    constexpr int MT = 2;
    constexpr int NT = (CFG == 0) ? 4 : 8;
    constexpr int NWC = (CFG == 0) ? 32 : 64;

    const __nv_bfloat16 *Ah, *Al, *Bh, *Bl;
    float* Cf = nullptr;
    float* Pf = nullptr;
    __nv_bfloat16 *Chi = nullptr, *Clo = nullptr;
    int M, N, K;
    if (CFG == 0) {
        Ah = d_Fhi; Al = d_Flo; Bh = d_IWhi; Bl = d_IWlo;
        Chi = d_Xhi; Clo = d_Xlo;
        M = NROWS; N = DMODEL; K = GENEF;
    } else {
        int dir = blockIdx.z;
        Ah = d_Xhi; Al = d_Xlo; Bh = d_Whi[dir]; Bl = d_Wlo[dir];
        Cf = d_Z[dir];
        Pf = d_P[dir];
        M = NROWS; N = DPROJ; K = DMODEL;
    }

    __shared__ __align__(16) __nv_bfloat16 sA[2][2][128 * SST];
    __shared__ __align__(16) __nv_bfloat16 sB[2][2][128 * SST];

    int tid = threadIdx.x;
    int row0 = blockIdx.y * BM;
    int col0 = blockIdx.x * 128;
    int lrow = tid >> 1;
    int seg = tid & 1;
    int lrowA = lrow & (BM - 1);

    int arow = row0 + lrowA;
    int brow = col0 + lrow;
    int arc = (arow < M) ? arow : (M - 1);
    int brc = (brow < N) ? brow : (N - 1);

    const __nv_bfloat16* pAh = Ah + (size_t)arc * K + seg * 8;
    const __nv_bfloat16* pAl = Al + (size_t)arc * K + seg * 8;
    const __nv_bfloat16* pBh = Bh + (size_t)brc * K + seg * 8;
    const __nv_bfloat16* pBl = Bl + (size_t)brc * K + seg * 8;

    unsigned dA0 = smem_u32(&sA[0][0][lrow * SST + seg * 8]);
    unsigned dA1 = smem_u32(&sA[0][1][lrow * SST + seg * 8]);
    unsigned dB0 = smem_u32(&sB[0][0][lrow * SST + seg * 8]);
    unsigned dB1 = smem_u32(&sB[0][1][lrow * SST + seg * 8]);
    const unsigned bufoff = (unsigned)(2 * 128 * SST * sizeof(__nv_bfloat16));

#define HG_STAGE(kc_, bb_)                                                     \
    {                                                                          \
        size_t o = (size_t)(kc_) * 16;                                         \
        unsigned bo = (bb_) ? bufoff : 0u;                                     \
        CPA16(dA0 + bo, pAh + o);                                              \
        CPA16(dA1 + bo, pAl + o);                                              \
        CPA16(dB0 + bo, pBh + o);                                              \
        CPA16(dB1 + bo, pBl + o);                                              \
    }

    HG_STAGE(0, 0);
    CP_COMMIT();

    int w = tid >> 5, l = tid & 31;
    int mw = (CFG == 0) ? (w >> 2) : (w >> 1);
    int nw = (CFG == 0) ? (w & 3) : (w & 1);
    int g = l >> 2, q = l & 3;

    int aoff = (mw * 32 + (l & 15)) * SST + (l >> 4) * 8;
    int boff = (nw * NWC + (l & 7) + (l >> 4) * 8) * SST + ((l >> 3) & 1) * 8;

    float c[MT][NT][4];
#pragma unroll
    for (int mt = 0; mt < MT; mt++)
#pragma unroll
        for (int nt = 0; nt < NT; nt++)
#pragma unroll
            for (int i = 0; i < 4; i++) c[mt][nt][i] = 0.f;

    const int NCH = K >> 4;
    for (int kc = 0; kc < NCH; kc++) {
        int buf = kc & 1;
        bool more = (kc + 1) < NCH;
        CP_WAIT0();
        __syncthreads();
        if (more) {
            HG_STAGE(kc + 1, buf ^ 1);
            CP_COMMIT();
        }

        unsigned a[MT][2][4], b[NT][2][2];
#pragma unroll
        for (int v = 0; v < 2; v++) {
#pragma unroll
            for (int mt = 0; mt < MT; mt++) {
                unsigned ad = smem_u32(&sA[buf][v][aoff + mt * 16 * SST]);
                LDSM_X4(a[mt][v][0], a[mt][v][1], a[mt][v][2], a[mt][v][3], ad);
            }
#pragma unroll
            for (int jp = 0; jp < NT / 2; jp++) {
                unsigned bd = smem_u32(&sB[buf][v][boff + jp * 16 * SST]);
                LDSM_X4(b[2 * jp][v][0], b[2 * jp][v][1],
                        b[2 * jp + 1][v][0], b[2 * jp + 1][v][1], bd);
            }
        }
#pragma unroll
        for (int mt = 0; mt < MT; mt++)
#pragma unroll
            for (int nt = 0; nt < NT; nt++) {
                MMA_BF16(c[mt][nt], a[mt][0], b[nt][0]);
                MMA_BF16(c[mt][nt], a[mt][0], b[nt][1]);
                MMA_BF16(c[mt][nt], a[mt][1], b[nt][0]);
            }
    }
#undef HG_STAGE

#pragma unroll
    for (int mt = 0; mt < MT; mt++) {
        int r0 = row0 + mw * 32 + mt * 16 + g;
#pragma unroll
        for (int nt = 0; nt < NT; nt++) {
            int cc = col0 + nw * NWC + nt * 8 + q * 2;
            if (cc >= N) continue;
            float b0 = bias ? bias[cc] : 0.f;
            float b1 = bias ? bias[cc + 1] : 0.f;
#pragma unroll
            for (int half = 0; half < 2; half++) {
                int r = r0 + half * 8;
                if (r >= M) continue;
                float v0 = c[mt][nt][half * 2 + 0] + b0;
                float v1 = c[mt][nt][half * 2 + 1] + b1;
                if (CFG != 0) {
                    if (cc < DIN) {
                        if (r < 2048) {
                            Pf[(size_t)r * DIN + cc] = fast_silu(v0);
                            Pf[(size_t)r * DIN + cc + 1] = fast_silu(v1);
                        }
                    } else {
                        *(float2*)&Cf[(size_t)r * N + cc] = make_float2(v0, v1);
                    }
                } else {
                    store_split(Chi, Clo, (size_t)r * N + cc, v0);
                    store_split(Chi, Clo, (size_t)r * N + cc + 1, v1);
                }
            }
        }
    }
}

// ------------------------- 3. causal depthwise conv + silu (float4) ----------
__global__ void conv_kernel(const float* __restrict__ cw_f, const float* __restrict__ cb_f,
                            const float* __restrict__ cw_b, const float* __restrict__ cb_b) {
    int bx = blockIdx.x;
    int dir = blockIdx.y;
    const float* cw = dir ? cw_b : cw_f;
    const float* cb = dir ? cb_b : cb_f;
    const float* Z = d_Z[dir];

    const float* rows[4];
    float* dst;
    if (bx < L_SEQ) {
        int t = bx;
        if ((dir == 0 && t < 4) || (dir == 1 && t < 1)) return;
        dst = d_xBCs[dir] + (size_t)t * CONVD;
#pragma unroll
        for (int k = 0; k < 4; k++) {
            int tau = dir ? (t + 3 - k) : (t - 3 + k);
            rows[k] = (tau <= L_SEQ - 1) ? (Z + (size_t)(tau - 1) * DPROJ + DIN) : nullptr;
        }
    } else {
        if (dir == 1) return;
        int idx = bx - L_SEQ;
        int b = idx >> 2;
        int t = idx & 3;
        dst = d_xBC0 + (size_t)(b * 4 + t) * CONVD;
#pragma unroll
        for (int k = 0; k < 4; k++) {
            int tau = t - 3 + k;
            rows[k] = (tau >= 0) ? (Z + (size_t)seq_row(b, tau) * DPROJ + DIN) : nullptr;
        }
    }
    for (int c4 = threadIdx.x; c4 < CONVD / 4; c4 += blockDim.x) {
        int c = c4 * 4;
        float4 acc = *(const float4*)(cb + c);
        float wq[4][4];
        *(float4*)wq[0] = *(const float4*)(cw + c * 4);
        *(float4*)wq[1] = *(const float4*)(cw + c * 4 + 4);
        *(float4*)wq[2] = *(const float4*)(cw + c * 4 + 8);
        *(float4*)wq[3] = *(const float4*)(cw + c * 4 + 12);
#pragma unroll
        for (int k = 0; k < 4; k++) {
            if (rows[k]) {
                float4 v = *(const float4*)(rows[k] + c);
                acc.x = fmaf(v.x, wq[0][k], acc.x);
                acc.y = fmaf(v.y, wq[1][k], acc.y);
                acc.z = fmaf(v.z, wq[2][k], acc.z);
                acc.w = fmaf(v.w, wq[3][k], acc.w);
            }
        }
        float4 o;
        o.x = fast_silu(acc.x);
        o.y = fast_silu(acc.y);
        o.z = fast_silu(acc.z);
        o.w = fast_silu(acc.w);
        *(float4*)(dst + c) = o;
    }
}

// ------------------------- 4. dt / dA per row --------------------------------
__global__ void dtda_kernel(const float* __restrict__ fdtb, const float* __restrict__ fAl,
                            const float* __restrict__ bdtb, const float* __restrict__ bAl) {
    int idx = blockIdx.x * blockDim.x + threadIdx.x;
    const int per = NROWS * NH;
    if (idx >= 2 * per) return;
    int dir = idx / per;
    int r = idx % per;
    int row = r >> 4;
    int h = r & 15;
    float raw = d_Z[dir][(size_t)row * DPROJ + (DIN + CONVD) + h] + (dir ? bdtb : fdtb)[h];
    float dtv = (raw > 20.f) ? raw : log1pf(expf(raw));
    float Al = (dir ? bAl : fAl)[h];
    d_dtr[dir][row * NH + h] = dtv;
    d_dAr[dir][row * NH + h] = expf(-expf(Al) * dtv);
}

// ------------------------- 4b. fwd decay cumprod (parallel) ------------------
__global__ void decay_kernel() {
    int tid = threadIdx.x;    // 512
    int h = tid >> 5;
    int lane = tid & 31;
    int s0 = lane * 64;
    int len = (s0 < TCOR) ? ((TCOR - s0 < 64) ? (TCOR - s0) : 64) : 0;
    float prod = 1.f;
    for (int i = 0; i < len; i++) prod *= d_dAr[0][(size_t)(3 + s0 + i) * NH + h];
    float inc = prod;
#pragma unroll
    for (int off = 1; off < 32; off <<= 1) {
        float v = __shfl_up_sync(0xffffffffu, inc, off);
        if (lane >= off) inc *= v;
    }
    float excl = __shfl_up_sync(0xffffffffu, inc, 1);
    if (lane == 0) excl = 1.f;
    float run = excl;
    for (int i = 0; i < len; i++) {
        run *= d_dAr[0][(size_t)(3 + s0 + i) * NH + h];
        d_decayf[h * TCOR + s0 + i] = run;
    }
}

// ------------------------- 4c. W4 --------------------------------------------
__global__ void w4_kernel() {
    int idx = threadIdx.x;   // 512
    if (idx >= BATCH * NH * 4) return;
    int b = idx >> 6, h = (idx >> 2) & 15, tau = idx & 3;
    int row_tau = (tau == 0) ? (2048 + b) : (tau - 1);
    float w = d_dtr[0][row_tau * NH + h];
    for (int s = tau + 1; s < 4; s++)
        w *= d_dAr[0][(s - 1) * NH + h];
    d_W4[idx] = w;
}

// ------------------------- 4d. dotCB -----------------------------------------
__global__ void dotcb_kernel() {
    int t = blockIdx.x + 4;       // 4..2048
    __shared__ float sC[128];
    int tid = threadIdx.x;        // 256 = 8 warps
    if (tid < 128) sC[tid] = d_xBCs[0][(size_t)t * CONVD + DIN + NS + tid];
    __syncthreads();
    int w = tid >> 5, l = tid & 31;
    for (int c = w; c < 32; c += 8) {
        const float* B0 = d_xBC0 + (size_t)c * CONVD + DIN;
        float acc = 0.f;
#pragma unroll
        for (int i = 0; i < 4; i++) acc = fmaf(B0[i * 32 + l], sC[i * 32 + l], acc);
#pragma unroll
        for (int off = 16; off; off >>= 1)
            acc += __shfl_xor_sync(0xffffffffu, acc, off);
        if (l == 0) d_dotCB[t * 32 + c] = acc;
    }
}

// ------------------------- 5. combined output vector -------------------------
__global__ void wcomb_kernel(const float* __restrict__ head_w,
                             const float* __restrict__ fow, const float* __restrict__ bow,
                             const float* __restrict__ fnw, const float* __restrict__ bnw) {
    int idx = blockIdx.x * blockDim.x + threadIdx.x;
    if (idx >= 2 * DIN) return;
    int dir = idx >> 10;
    int j = idx & 1023;
    const float* ow = dir ? bow : fow;
    float acc = 0.f;
    for (int i = 0; i < DMODEL; i++) acc = fmaf(ow[(size_t)i * DIN + j], head_w[i], acc);
    d_wcomb[dir][j] = acc * (dir ? bnw : fnw)[j];
}

// ------------------------- 6a. fwd per-batch prefix scan (t=0..3) ------------
__global__ __launch_bounds__(128) void prefix_kernel(const float* __restrict__ fD) {
    int blk = blockIdx.x;
    int b = blk >> 4;
    int h = blk & 15;
    int tid = threadIdx.x;
    int p = tid & 63;
    int nh = tid >> 6;
    float Dh = fD[h];

    __shared__ __align__(16) float sB[128], sC[128], sx[64];

    unsigned long long hs2[32];
#pragma unroll
    for (int i = 0; i < 32; i++) hs2[i] = 0ull;

    for (int t = 0; t < 4; t++) {
        const float* pp = xbc_fwd_ptr(b, t);
        sB[tid] = pp[DIN + tid];
        sC[tid] = pp[DIN + NS + tid];
        if (tid < 64) sx[tid] = pp[h * HD + tid];
        __syncthreads();
        int row = (t == 0) ? (2048 + b) : (t - 1);
        float dtv = d_dtr[0][row * NH + h];
        float dAv = d_dAr[0][row * NH + h];
        float xv = sx[p];
        unsigned long long coef2 = pack2(dtv * xv);
        unsigned long long dA2 = pack2(dAv);
        const ulonglong2* B4 = (const ulonglong2*)(sB + nh * 64);
        const ulonglong2* C4 = (const ulonglong2*)(sC + nh * 64);
        unsigned long long a0 = 0ull, a1 = 0ull;
#pragma unroll
        for (int i = 0; i < 16; i++) {
            ulonglong2 bv = B4[i], cv = C4[i];
            unsigned long long tm;
            MUL2(tm, coef2, bv.x);
            FMA2(hs2[2 * i + 0], dA2, hs2[2 * i + 0], tm);
            FMA2(a0, hs2[2 * i + 0], cv.x, a0);
            MUL2(tm, coef2, bv.y);
            FMA2(hs2[2 * i + 1], dA2, hs2[2 * i + 1], tm);
            FMA2(a1, hs2[2 * i + 1], cv.y, a1);
        }
        ADD2(a0, a0, a1);
        float part = sum2(a0);
        if (nh == 0) part = fmaf(Dh, xv, part);
        if (t >= 1)
            d_ypre[((size_t)(b * 3 + (t - 1)) * 16 + h) * 128 + tid] = part;
        __syncthreads();
    }
}

// ------------------------- 6b. shared scans — p-split, no atomics ------------
__global__ __launch_bounds__(128) void scan_shared(const float* __restrict__ fD,
                                                   const float* __restrict__ bD) {
    int blk = blockIdx.x;          // 0..255
    int dir = blk >> 7;
    int rest = blk & 127;
    int h = rest >> 3;
    int pq = rest & 7;
    int tid = threadIdx.x;
    int p8 = tid & 7;
    int nsix = tid >> 3;
    float Dh = (dir ? bD : fD)[h];
    const float* xbc = d_xBCs[dir];
    const float* dtr = d_dtr[dir];
    const float* dAr = d_dAr[dir];
    float* ysum = d_ysum[dir];

    int S = dir ? 2048 : TCOR;
    int nch = (S + TC - 1) / TC;

    __shared__ __align__(16) float sB[2][TC][128];
    __shared__ __align__(16) float sC[2][TC][128];
    __shared__ __align__(16) float sx[2][TC][8];
    __shared__ float sdt[2][TC], sdA[2][TC];
    __shared__ __align__(16) float sy[TC][128];

    unsigned long long hs2[4] = {0ull, 0ull, 0ull, 0ull};

    float4 rB[4], rC[4], rx;
    float rdt = 0.f, rdA = 0.f;

#define SCAN_LOAD(s0_)                                                          \
    {                                                                           \
        int lim = S - 1 - (s0_);                                                \
        _Pragma("unroll")                                                       \
        for (int k = 0; k < 4; k++) {                                           \
            int idx = tid + k * 128;                                            \
            int j = idx >> 5; if (j > lim) j = lim;                             \
            int tt = dir ? (2048 - ((s0_) + j)) : (4 + (s0_) + j);              \
            const float* rowp = xbc + (size_t)tt * CONVD + DIN;                 \
            rB[k] = ((const float4*)rowp)[idx & 31];                            \
            rC[k] = ((const float4*)(rowp + NS))[idx & 31];                     \
        }                                                                       \
        if (tid < 2 * TC) {                                                     \
            int j = tid >> 1; if (j > lim) j = lim;                             \
            int tt = dir ? (2048 - ((s0_) + j)) : (4 + (s0_) + j);              \
            rx = ((const float4*)(xbc + (size_t)tt * CONVD + h * HD + pq * 8))[tid & 1]; \
        }                                                                       \
        if (tid < TC) {                                                         \
            int j = (tid > lim) ? lim : tid;                                    \
            int tt = dir ? (2048 - ((s0_) + j)) : (4 + (s0_) + j);              \
            rdt = dtr[(tt - 1) * NH + h];                                       \
            rdA = dAr[(tt - 1) * NH + h];                                       \
        }                                                                       \
    }
#define SCAN_STORE(bb_)                                                         \
    {                                                                           \
        _Pragma("unroll")                                                       \
        for (int k = 0; k < 4; k++) {                                           \
            int idx = tid + k * 128;                                            \
            *(float4*)&sB[bb_][idx >> 5][(idx & 31) * 4] = rB[k];               \
            *(float4*)&sC[bb_][idx >> 5][(idx & 31) * 4] = rC[k];               \
        }                                                                       \
        if (tid < 2 * TC) *(float4*)&sx[bb_][tid >> 1][(tid & 1) * 4] = rx;     \
        if (tid < TC) { sdt[bb_][tid] = rdt; sdA[bb_][tid] = rdA; }             \
    }

    SCAN_LOAD(0);
    SCAN_STORE(0);
    __syncthreads();

    for (int c = 0; c < nch; c++) {
        int s0 = c * TC;
        int cnt = (S - s0 < TC) ? (S - s0) : TC;
        bool more = (c + 1) < nch;
        if (more) SCAN_LOAD(s0 + TC);
        int bb = c & 1;
        for (int j = 0; j < cnt; j++) {
            float xv = sx[bb][j][p8];
            unsigned long long coef2 = pack2(sdt[bb][j] * xv);
            unsigned long long dA2 = pack2(sdA[bb][j]);
            const ulonglong2* B4 = (const ulonglong2*)&sB[bb][j][nsix * 8];
            const ulonglong2* C4 = (const ulonglong2*)&sC[bb][j][nsix * 8];
            ulonglong2 bv0 = B4[0], cv0 = C4[0];
            ulonglong2 bv1 = B4[1], cv1 = C4[1];
            unsigned long long a0 = 0ull, a1 = 0ull, tm;
            MUL2(tm, coef2, bv0.x);
            FMA2(hs2[0], dA2, hs2[0], tm);
            FMA2(a0, hs2[0], cv0.x, a0);
            MUL2(tm, coef2, bv0.y);
            FMA2(hs2[1], dA2, hs2[1], tm);
            FMA2(a1, hs2[1], cv0.y, a1);
            MUL2(tm, coef2, bv1.x);
            FMA2(hs2[2], dA2, hs2[2], tm);
            FMA2(a0, hs2[2], cv1.x, a0);
            MUL2(tm, coef2, bv1.y);
            FMA2(hs2[3], dA2, hs2[3], tm);
            FMA2(a1, hs2[3], cv1.y, a1);
            ADD2(a0, a0, a1);
            sy[j][tid] = sum2(a0);
        }
        if (more) SCAN_STORE(bb ^ 1);
        __syncthreads();
        {
            int jo = tid >> 3;
            int po = tid & 7;
            if (jo < cnt) {
                const float* sp = &sy[jo][po];
                float s = 0.f;
#pragma unroll
                for (int k = 0; k < 16; k++) s += sp[k * 8];
                s = fmaf(Dh, sx[bb][jo][po], s);
                int tt = dir ? (2048 - (s0 + jo)) : (4 + s0 + jo);
                ysum[(size_t)tt * 1024 + h * 64 + pq * 8 + po] = s;
            }
        }
        __syncthreads();
    }
#undef SCAN_LOAD
#undef SCAN_STORE
}

// ------------------------- 7. gate + RMSnorm + fused head (per-t, all b) -----
__global__ __launch_bounds__(256) void final_kernel(const float* __restrict__ head_b,
                                                    float* __restrict__ out) {
    int t = blockIdx.x + 1;     // 1..2048
    int tid = threadIdx.x;      // 256
    __shared__ float cco[8][64];
    __shared__ float sh[8][18];

    if (t >= 4) {
        for (int i = tid; i < 512; i += 256) {
            int b = i >> 6;
            int r = i & 63;             // h*4+tau
            int hh = r >> 2, tau = r & 3;
            cco[b][r] = d_decayf[hh * TCOR + (t - 4)] *
                        d_W4[(b * 16 + hh) * 4 + tau] *
                        d_dotCB[t * 32 + b * 4 + tau];
        }
    }
    __syncthreads();

    int j0 = tid * 4;
    int h = tid >> 4;
    float4 ysf4 = *(const float4*)&d_ysum[0][(size_t)t * DIN + j0];
    float4 ysb4 = *(const float4*)&d_ysum[1][(size_t)t * DIN + j0];
    float4 pf4 = *(const float4*)&d_P[0][(size_t)(t - 1) * DIN + j0];
    float4 pb4 = *(const float4*)&d_P[1][(size_t)(t - 1) * DIN + j0];
    float4 w04 = *(const float4*)&d_wcomb[0][j0];
    float4 w14 = *(const float4*)&d_wcomb[1][j0];

    float ssqb = 0.f, sdotb = 0.f;
    {
        float g;
        g = ysb4.x * pb4.x; ssqb = fmaf(g, g, ssqb); sdotb = fmaf(g, w14.x, sdotb);
        g = ysb4.y * pb4.y; ssqb = fmaf(g, g, ssqb); sdotb = fmaf(g, w14.y, sdotb);
        g = ysb4.z * pb4.z; ssqb = fmaf(g, g, ssqb); sdotb = fmaf(g, w14.z, sdotb);
        g = ysb4.w * pb4.w; ssqb = fmaf(g, g, ssqb); sdotb = fmaf(g, w14.w, sdotb);
    }

    float ssqf[8], sdotf[8];
    if (t >= 4) {
#pragma unroll
        for (int b = 0; b < 8; b++) {
            const float* xbb = d_xBC0 + (size_t)b * 4 * CONVD + j0;
            float4 x0 = *(const float4*)&xbb[0];
            float4 x1 = *(const float4*)&xbb[CONVD];
            float4 x2 = *(const float4*)&xbb[2 * CONVD];
            float4 x3 = *(const float4*)&xbb[3 * CONVD];
            float cc0 = cco[b][h * 4 + 0], cc1 = cco[b][h * 4 + 1];
            float cc2 = cco[b][h * 4 + 2], cc3 = cco[b][h * 4 + 3];
            float sq = 0.f, sd = 0.f, yf, g;
            yf = ysf4.x + cc0 * x0.x + cc1 * x1.x + cc2 * x2.x + cc3 * x3.x;
            g = yf * pf4.x; sq = fmaf(g, g, sq); sd = fmaf(g, w04.x, sd);
            yf = ysf4.y + cc0 * x0.y + cc1 * x1.y + cc2 * x2.y + cc3 * x3.y;
            g = yf * pf4.y; sq = fmaf(g, g, sq); sd = fmaf(g, w04.y, sd);
            yf = ysf4.z + cc0 * x0.z + cc1 * x1.z + cc2 * x2.z + cc3 * x3.z;
            g = yf * pf4.z; sq = fmaf(g, g, sq); sd = fmaf(g, w04.z, sd);
            yf = ysf4.w + cc0 * x0.w + cc1 * x1.w + cc2 * x2.w + cc3 * x3.w;
            g = yf * pf4.w; sq = fmaf(g, g, sq); sd = fmaf(g, w04.w, sd);
            ssqf[b] = sq; sdotf[b] = sd;
        }
    } else {
        int p0 = j0 & 63;
#pragma unroll
        for (int b = 0; b < 8; b++) {
            const float* yp = d_ypre + ((size_t)(b * 3 + (t - 1)) * 16 + h) * 128;
            float sq = 0.f, sd = 0.f;
            float pf[4] = {pf4.x, pf4.y, pf4.z, pf4.w};
            float w0[4] = {w04.x, w04.y, w04.z, w04.w};
#pragma unroll
            for (int k = 0; k < 4; k++) {
                float yf = yp[p0 + k] + yp[64 + p0 + k];
                float g = yf * pf[k];
                sq = fmaf(g, g, sq); sd = fmaf(g, w0[k], sd);
            }
            ssqf[b] = sq; sdotf[b] = sd;
        }
    }

#pragma unroll
    for (int off = 16; off; off >>= 1) {
        ssqb += __shfl_xor_sync(0xffffffffu, ssqb, off);
        sdotb += __shfl_xor_sync(0xffffffffu, sdotb, off);
#pragma unroll
        for (int b = 0; b < 8; b++) {
            ssqf[b] += __shfl_xor_sync(0xffffffffu, ssqf[b], off);
            sdotf[b] += __shfl_xor_sync(0xffffffffu, sdotf[b], off);
        }
    }
    int w = tid >> 5, l = tid & 31;
    if (l == 0) {
        sh[w][0] = ssqb; sh[w][1] = sdotb;
#pragma unroll
        for (int b = 0; b < 8; b++) { sh[w][2 + b] = ssqf[b]; sh[w][10 + b] = sdotf[b]; }
    }
    __syncthreads();
    if (tid < 8) {
        float qb = 0.f, db = 0.f, a = 0.f, d = 0.f;
        for (int i = 0; i < 8; i++) {
            qb += sh[i][0]; db += sh[i][1];
            a += sh[i][2 + tid]; d += sh[i][10 + tid];
        }
        float resb = rsqrtf(qb * (1.f / 1024.f) + 1e-5f) * db;
        float resf = rsqrtf(a * (1.f / 1024.f) + 1e-5f) * d;
        out[tid * 2048 + (t - 1)] = resf + resb + head_b[0];
    }
}

// ------------------------- launch --------------------------------------------
extern "C" void kernel_launch(void* const* d_in, const int* in_sizes, int n_in,
                              void* d_out, int out_size) {
    const int* pidx            = (const int*)d_in[0];
    const int* chridx          = (const int*)d_in[1];
    const float* locus_fourier = (const float*)d_in[2];
    const float* pathway       = (const float*)d_in[3];
    const float* pert_emb      = (const float*)d_in[4];
    const float* gene_id       = (const float*)d_in[5];
    const float* chr_emb       = (const float*)d_in[6];
    const float* locus_w       = (const float*)d_in[7];
    const float* locus_b       = (const float*)d_in[8];
    const float* cond_w        = (const float*)d_in[9];
    const float* cond_b        = (const float*)d_in[10];
    const float* in_w          = (const float*)d_in[11];
    const float* in_b          = (const float*)d_in[12];
    const float* head_w        = (const float*)d_in[13];
    const float* head_b        = (const float*)d_in[14];
    const float* f_in_w        = (const float*)d_in[15];
    const float* f_conv_w      = (const float*)d_in[16];
    const float* f_conv_b      = (const float*)d_in[17];
    const float* f_dt_bias     = (const float*)d_in[18];
    const float* f_A_log       = (const float*)d_in[19];
    const float* f_D           = (const float*)d_in[20];
    const float* f_norm_w      = (const float*)d_in[21];
    const float* f_out_w       = (const float*)d_in[22];
    const float* b_in_w        = (const float*)d_in[23];
    const float* b_conv_w      = (const float*)d_in[24];
    const float* b_conv_b      = (const float*)d_in[25];
    const float* b_dt_bias     = (const float*)d_in[26];
    const float* b_A_log       = (const float*)d_in[27];
    const float* b_D           = (const float*)d_in[28];
    const float* b_norm_w      = (const float*)d_in[29];
    const float* b_out_w       = (const float*)d_in[30];
    float* out = (float*)d_out;

    feat_kernel<<<NROWS, 128>>>(pidx, chridx, locus_fourier, pathway, pert_emb,
                                gene_id, chr_emb, locus_w, locus_b, cond_w, cond_b);
    cvt_weights<<<(DPROJ * DMODEL + 255) / 256, 256>>>(f_in_w, b_in_w, in_w);

    // X = feat @ in_w^T + in_b (64x128 tiles, cp.async staging)
    hgemm<0><<<dim3(4, 33), 256>>>(in_b);
    // Z_dir = X @ W^T (128x128 tiles, both dirs; z-cols -> silu -> d_P fused)
    hgemm<1><<<dim3(19, 17, 2), 256>>>(nullptr);

    conv_kernel<<<dim3(L_SEQ + 32, 2), 256>>>(f_conv_w, f_conv_b, b_conv_w, b_conv_b);

    dtda_kernel<<<(2 * NROWS * NH + 255) / 256, 256>>>(f_dt_bias, f_A_log, b_dt_bias, b_A_log);
    decay_kernel<<<1, 512>>>();
    w4_kernel<<<1, 512>>>();
    dotcb_kernel<<<TCOR, 256>>>();

    wcomb_kernel<<<(2 * DIN + 255) / 256, 256>>>(head_w, f_out_w, b_out_w, f_norm_w, b_norm_w);

    prefix_kernel<<<128, 128>>>(f_D);

    // R15 scan (measured best): register-staged chunks, per-chunk parallel reduce
    scan_shared<<<256, 128>>>(f_D, b_D);

    final_kernel<<<2048, 256>>>(head_b, out);
}